// round 7
// baseline (speedup 1.0000x reference)
#include <cuda_runtime.h>
#include <cuda_bf16.h>
#include <cstdint>

// ---------------------------------------------------------------------------
// Problem dims
// ---------------------------------------------------------------------------
#define B_BATCH   128
#define T_STEPS   500
#define K_DIM     700
#define KP        704                       // K padded to multiple of 32
#define N_DIM     1024
#define M_DIM     (B_BATCH * T_STEPS)       // 64000

// LIF constants
#define PHI_C    0.36787944117144233f
#define GAMMA_C  0.8187307530779818f
#define BETA_C   0.9048374180359595f
#define U_TH_C   1.0f

#define EPS_FLAG 1.0e-3f                    // near-threshold flag window

// ---------------------------------------------------------------------------
// Device scratch
// ---------------------------------------------------------------------------
__device__ float g_inputs[(size_t)M_DIM * N_DIM];
__device__ __nv_bfloat16 g_asplit[3ull * M_DIM * KP];
__device__ __nv_bfloat16 g_bsplit[3ull * N_DIM * KP];
__device__ unsigned char g_flags[B_BATCH * N_DIM];

#define A_PLANE ((size_t)M_DIM * KP)
#define B_PLANE ((size_t)N_DIM * KP)

// ---------------------------------------------------------------------------
// Split kernel: fp32 -> 3x bf16 (hi, mid, lo), K padded with zeros
// ---------------------------------------------------------------------------
__global__ __launch_bounds__(256) void split_kernel(
    const float* __restrict__ src,          // [rows, K_DIM]
    __nv_bfloat16* __restrict__ dst,        // [3, rows, KP]
    int rows, size_t plane)
{
    int idx = blockIdx.x * blockDim.x + threadIdx.x;
    int r = idx / (KP / 8);
    int u = idx % (KP / 8);
    if (r >= rows) return;
    int k = u * 8;

    __nv_bfloat16 h0[8], h1[8], h2[8];
#pragma unroll
    for (int i = 0; i < 8; i++) {
        float x = (k + i < K_DIM) ? src[(size_t)r * K_DIM + k + i] : 0.0f;
        __nv_bfloat16 a = __float2bfloat16(x);
        float r1 = x - __bfloat162float(a);
        __nv_bfloat16 b = __float2bfloat16(r1);
        float r2 = r1 - __bfloat162float(b);
        __nv_bfloat16 c = __float2bfloat16(r2);
        h0[i] = a; h1[i] = b; h2[i] = c;
    }
    size_t off = (size_t)r * KP + k;
    *(uint4*)(dst + off)             = *(uint4*)h0;
    *(uint4*)(dst + plane + off)     = *(uint4*)h1;
    *(uint4*)(dst + 2 * plane + off) = *(uint4*)h2;
}

// ---------------------------------------------------------------------------
// bf16 mma.sync GEMM:  C[m,n] = sum_k A[m,k]*B[n,k]  (6 split cross-products)
// Block 128x128, K-chunk 32, 3 cp.async stages, 8 warps (2x4), warp 64x32.
// ---------------------------------------------------------------------------
#define BKC        32
#define NCHUNK     (KP / BKC)               // 22
#define ROWSTRIDE  80                       // (32+8) bf16 = 80 B, ldmatrix-safe
#define PLANE_B    (128 * ROWSTRIDE)        // 10240 B per plane tile
#define STAGE_B    (6 * PLANE_B)            // 61440 B
#define NSTAGE     3
#define DYN_SMEM   (NSTAGE * STAGE_B)       // 184320 B

__device__ __forceinline__ uint32_t smem_u32(const void* p) {
    uint32_t a;
    asm("{ .reg .u64 t; cvta.to.shared.u64 t, %1; cvt.u32.u64 %0, t; }" : "=r"(a) : "l"(p));
    return a;
}

__device__ __forceinline__ void ldsm_x4(uint32_t addr, uint32_t& r0, uint32_t& r1,
                                        uint32_t& r2, uint32_t& r3) {
    asm volatile("ldmatrix.sync.aligned.m8n8.x4.shared.b16 {%0,%1,%2,%3}, [%4];"
                 : "=r"(r0), "=r"(r1), "=r"(r2), "=r"(r3) : "r"(addr));
}

__device__ __forceinline__ void mma16816(float* d, const uint32_t* a, const uint32_t* b) {
    asm volatile(
        "mma.sync.aligned.m16n8k16.row.col.f32.bf16.bf16.f32 "
        "{%0,%1,%2,%3}, {%4,%5,%6,%7}, {%8,%9}, {%0,%1,%2,%3};"
        : "+f"(d[0]), "+f"(d[1]), "+f"(d[2]), "+f"(d[3])
        : "r"(a[0]), "r"(a[1]), "r"(a[2]), "r"(a[3]), "r"(b[0]), "r"(b[1]));
}

__device__ __forceinline__ void load_stage(
    int chunk, int s, int tid, int m0, int n0, uint32_t smem_base,
    const __nv_bfloat16* __restrict__ Asp, const __nv_bfloat16* __restrict__ Bsp)
{
    const int k0 = chunk * BKC;
    const uint32_t sb = smem_base + s * STAGE_B;
#pragma unroll
    for (int it = 0; it < 12; ++it) {
        int idx  = tid + it * 256;
        int tile = idx >> 9;
        int rem  = idx & 511;
        int r    = rem >> 2;
        int c16  = rem & 3;
        const __nv_bfloat16* src;
        if (tile < 3)
            src = Asp + (size_t)tile * A_PLANE + (size_t)(m0 + r) * KP + k0 + c16 * 8;
        else
            src = Bsp + (size_t)(tile - 3) * B_PLANE + (size_t)(n0 + r) * KP + k0 + c16 * 8;
        uint32_t dst = sb + tile * PLANE_B + r * ROWSTRIDE + c16 * 16;
        asm volatile("cp.async.cg.shared.global [%0], [%1], 16;" :: "r"(dst), "l"(src));
    }
    asm volatile("cp.async.commit_group;" ::: "memory");
}

__global__ __launch_bounds__(256, 1) void gemm_mma_kernel(
    const __nv_bfloat16* __restrict__ Asp,
    const __nv_bfloat16* __restrict__ Bsp,
    float* __restrict__ C)
{
    extern __shared__ __align__(128) char smem[];
    const uint32_t smem_base = smem_u32(smem);
    const int tid    = threadIdx.x;
    const int lane   = tid & 31;
    const int wid    = tid >> 5;
    const int warp_m = wid >> 2;
    const int warp_n = wid & 3;
    const int m0     = blockIdx.y * 128;
    const int n0     = blockIdx.x * 128;

    float acc[4][4][4];
#pragma unroll
    for (int i = 0; i < 4; i++)
#pragma unroll
        for (int j = 0; j < 4; j++)
#pragma unroll
            for (int f = 0; f < 4; f++) acc[i][j][f] = 0.f;

    load_stage(0, 0, tid, m0, n0, smem_base, Asp, Bsp);
    load_stage(1, 1, tid, m0, n0, smem_base, Asp, Bsp);

    const uint32_t a_row = warp_m * 64 + (lane & 15);
    const uint32_t a_kb  = ((lane >> 4) & 1) * 16;
    const uint32_t b_row = warp_n * 32 + ((lane >> 4) & 1) * 8 + (lane & 7);
    const uint32_t b_kb  = ((lane >> 3) & 1) * 16;

    for (int c = 0; c < NCHUNK; ++c) {
        const int s = c % NSTAGE;
        if (c == NCHUNK - 1)
            asm volatile("cp.async.wait_group 0;" ::: "memory");
        else
            asm volatile("cp.async.wait_group 1;" ::: "memory");
        __syncthreads();

        if (c + 2 < NCHUNK)
            load_stage(c + 2, (c + 2) % NSTAGE, tid, m0, n0, smem_base, Asp, Bsp);

        const uint32_t sA = smem_base + s * STAGE_B;
        const uint32_t sB = sA + 3 * PLANE_B;

#pragma unroll
        for (int ks = 0; ks < 2; ++ks) {
            uint32_t bf[3][4][2];
#pragma unroll
            for (int q = 0; q < 3; ++q) {
#pragma unroll
                for (int jb = 0; jb < 2; ++jb) {
                    uint32_t addr = sB + q * PLANE_B
                                  + (b_row + jb * 16) * ROWSTRIDE + ks * 32 + b_kb;
                    ldsm_x4(addr, bf[q][2 * jb][0], bf[q][2 * jb][1],
                                  bf[q][2 * jb + 1][0], bf[q][2 * jb + 1][1]);
                }
            }
#pragma unroll
            for (int p = 0; p < 3; ++p) {
                uint32_t af[4][4];
#pragma unroll
                for (int im = 0; im < 4; ++im) {
                    uint32_t addr = sA + p * PLANE_B
                                  + (a_row + im * 16) * ROWSTRIDE + ks * 32 + a_kb;
                    ldsm_x4(addr, af[im][0], af[im][1], af[im][2], af[im][3]);
                }
#pragma unroll
                for (int q = 0; q < 3; ++q) {
                    if (p + q > 2) continue;
#pragma unroll
                    for (int im = 0; im < 4; ++im)
#pragma unroll
                        for (int jn = 0; jn < 4; ++jn)
                            mma16816(acc[im][jn], af[im], bf[q][jn]);
                }
            }
        }
        __syncthreads();
    }

    const int erow = lane >> 2;
    const int ecol = (lane & 3) * 2;
#pragma unroll
    for (int im = 0; im < 4; ++im) {
#pragma unroll
        for (int jn = 0; jn < 4; ++jn) {
            float* cp = C + (size_t)(m0 + warp_m * 64 + im * 16 + erow) * N_DIM
                          + n0 + warp_n * 32 + jn * 8 + ecol;
            *(float2*)cp = make_float2(acc[im][jn][0], acc[im][jn][1]);
            *(float2*)(cp + 8 * N_DIM) = make_float2(acc[im][jn][2], acc[im][jn][3]);
        }
    }
}

// ---------------------------------------------------------------------------
// LIF scan + near-threshold flagging: one thread per (b, h)
// ---------------------------------------------------------------------------
__global__ __launch_bounds__(256) void lif_scan_flag_kernel(
    const float* __restrict__ inp,
    float* __restrict__ Uo,
    float* __restrict__ So,
    unsigned char* __restrict__ flags)
{
    int idx = blockIdx.x * blockDim.x + threadIdx.x;
    int b = idx >> 10;
    int h = idx & (N_DIM - 1);
    size_t base = (size_t)b * T_STEPS * N_DIM + h;

    const float* ip = inp + base;
    float* up = Uo + base;
    float* sp = So + base;

    up[0] = 0.0f;
    sp[0] = 0.0f;

    float H = 0.f, I = 0.f, U = 0.f, S = 0.f;
    int flagged = 0;
#pragma unroll 4
    for (int t = 1; t < T_STEPS; t++) {
        float x  = ip[(size_t)(t - 1) * N_DIM];
        float Hn = PHI_C * H + x;
        float In = GAMMA_C * I + H;
        float Un = BETA_C * (U - I) - S;
        float Sn = (Un > U_TH_C) ? 1.0f : 0.0f;
        flagged |= (fabsf(Un - U_TH_C) < EPS_FLAG) ? 1 : 0;
        up[(size_t)t * N_DIM] = Un;
        sp[(size_t)t * N_DIM] = Sn;
        H = Hn; I = In; U = Un; S = Sn;
    }
    flags[idx] = (unsigned char)flagged;
}

// ---------------------------------------------------------------------------
// Repair kernel: bit-exact recompute of flagged channels.
// One block per batch b. Processes up to 8 flagged h per pass.
// inputs[b,t,h] = ascending-k fp32 FMA chain (matches cublas / R1 bitwise),
// then the scan is replayed with identical expressions.
// ---------------------------------------------------------------------------
#define NH_BATCH 8
// dynamic smem floats: sX 500*33 = 16500, sW 8*704 = 5632, sInp 8*500 = 4000
#define RPR_SX    0
#define RPR_SW    16500
#define RPR_SINP  (16500 + 5632)
#define RPR_SMEM  ((16500 + 5632 + 4000) * 4)

__global__ __launch_bounds__(512) void lif_repair_kernel(
    const float* __restrict__ X,     // [B, T, K_DIM]
    const float* __restrict__ W,     // [N, K_DIM]
    const unsigned char* __restrict__ flags,
    float* __restrict__ Uo,
    float* __restrict__ So)
{
    extern __shared__ float rsm[];
    float* sX   = rsm + RPR_SX;
    float* sW   = rsm + RPR_SW;
    float* sInp = rsm + RPR_SINP;

    __shared__ int hlist[N_DIM];
    __shared__ int hcount;

    const int b   = blockIdx.x;
    const int tid = threadIdx.x;

    if (tid == 0) {
        int cnt = 0;
        for (int h = 0; h < N_DIM; ++h)
            if (flags[b * N_DIM + h]) hlist[cnt++] = h;
        hcount = cnt;
    }
    __syncthreads();
    const int nflag = hcount;

    for (int bi = 0; bi < nflag; bi += NH_BATCH) {
        const int nh = min(NH_BATCH, nflag - bi);

        // load W rows for this batch of channels
        for (int i = tid; i < nh * 704; i += 512) {
            int j = i / 704, k = i - j * 704;
            sW[j * 704 + k] = (k < K_DIM)
                ? W[(size_t)hlist[bi + j] * K_DIM + k] : 0.f;
        }
        __syncthreads();

        float c8[NH_BATCH];
#pragma unroll
        for (int j = 0; j < NH_BATCH; ++j) c8[j] = 0.f;

        for (int kc = 0; kc < K_DIM; kc += 32) {
            const int kw = (K_DIM - kc < 32) ? (K_DIM - kc) : 32;
            // cooperative coalesced load of X[b, :, kc..kc+kw)
            for (int i = tid; i < T_STEPS * kw; i += 512) {
                int tt = i / kw, kk = i - tt * kw;
                sX[tt * 33 + kk] = X[((size_t)b * T_STEPS + tt) * K_DIM + kc + kk];
            }
            __syncthreads();
            if (tid < T_STEPS) {
#pragma unroll
                for (int j = 0; j < NH_BATCH; ++j) {
                    float c = c8[j];
                    for (int kk = 0; kk < kw; ++kk)
                        c = fmaf(sX[tid * 33 + kk], sW[j * 704 + kc + kk], c);
                    c8[j] = c;
                }
            }
            __syncthreads();
        }

        if (tid < T_STEPS) {
#pragma unroll
            for (int j = 0; j < NH_BATCH; ++j)
                if (j < nh) sInp[j * T_STEPS + tid] = c8[j];
        }
        __syncthreads();

        // replay the scan for each repaired channel (thread j handles one)
        if (tid < nh) {
            const int h = hlist[bi + tid];
            size_t base = (size_t)b * T_STEPS * N_DIM + h;
            Uo[base] = 0.0f;
            So[base] = 0.0f;
            float H = 0.f, I = 0.f, U = 0.f, S = 0.f;
            for (int t = 1; t < T_STEPS; t++) {
                float x  = sInp[tid * T_STEPS + (t - 1)];
                float Hn = PHI_C * H + x;
                float In = GAMMA_C * I + H;
                float Un = BETA_C * (U - I) - S;
                float Sn = (Un > U_TH_C) ? 1.0f : 0.0f;
                Uo[base + (size_t)t * N_DIM] = Un;
                So[base + (size_t)t * N_DIM] = Sn;
                H = Hn; I = In; U = Un; S = Sn;
            }
        }
        __syncthreads();
    }
}

// ---------------------------------------------------------------------------
extern "C" void kernel_launch(void* const* d_in, const int* in_sizes, int n_in,
                              void* d_out, int out_size)
{
    const float* X = (const float*)d_in[0];  // [128, 500, 700]
    const float* W = (const float*)d_in[1];  // [1024, 700]
    float* out = (float*)d_out;

    float* inputs;           cudaGetSymbolAddress((void**)&inputs, g_inputs);
    __nv_bfloat16* asplit;   cudaGetSymbolAddress((void**)&asplit, g_asplit);
    __nv_bfloat16* bsplit;   cudaGetSymbolAddress((void**)&bsplit, g_bsplit);
    unsigned char* flags;    cudaGetSymbolAddress((void**)&flags, g_flags);

    cudaFuncSetAttribute(gemm_mma_kernel,
                         cudaFuncAttributeMaxDynamicSharedMemorySize, DYN_SMEM);
    cudaFuncSetAttribute(lif_repair_kernel,
                         cudaFuncAttributeMaxDynamicSharedMemorySize, RPR_SMEM);

    // 1. split into bf16 planes (K padded 700 -> 704)
    split_kernel<<<(M_DIM * (KP / 8) + 255) / 256, 256>>>(X, asplit, M_DIM, A_PLANE);
    split_kernel<<<(N_DIM * (KP / 8) + 255) / 256, 256>>>(W, bsplit, N_DIM, B_PLANE);

    // 2. tensor-core GEMM
    dim3 ggrid(N_DIM / 128, M_DIM / 128);
    gemm_mma_kernel<<<ggrid, 256, DYN_SMEM>>>(asplit, bsplit, inputs);

    // 3. LIF scan + flag near-threshold channels
    float* Uo = out;
    float* So = out + (size_t)B_BATCH * T_STEPS * N_DIM;
    lif_scan_flag_kernel<<<(B_BATCH * N_DIM) / 256, 256>>>(inputs, Uo, So, flags);

    // 4. bit-exact repair of flagged channels
    lif_repair_kernel<<<B_BATCH, 512, RPR_SMEM>>>(X, W, flags, Uo, So);
}

// round 8
// speedup vs baseline: 2.7471x; 2.7471x over previous
#include <cuda_runtime.h>
#include <cuda_bf16.h>
#include <cstdint>

#define B_BATCH   128
#define T_STEPS   500
#define K_DIM     700
#define KP        704
#define N_DIM     1024
#define M_DIM     64000

#define PHI_C    0.36787944117144233f
#define GAMMA_C  0.8187307530779818f
#define BETA_C   0.9048374180359595f
#define U_TH_C   1.0f
#define EPS_FLAG 2.0e-4f

__device__ float g_inputs[(size_t)M_DIM * N_DIM];
__device__ __nv_bfloat16 g_asplit[3ull * M_DIM * KP];
__device__ __nv_bfloat16 g_bsplit[3ull * N_DIM * KP];
__device__ unsigned char g_flags[B_BATCH * N_DIM];

#define A_PLANE ((size_t)M_DIM * KP)
#define B_PLANE ((size_t)N_DIM * KP)

// ---------------------------------------------------------------------------
// Split: fp32 -> 3x bf16 planes (hi, mid, lo), K zero-padded to 704
// ---------------------------------------------------------------------------
__global__ __launch_bounds__(256) void split_kernel(
    const float* __restrict__ src, __nv_bfloat16* __restrict__ dst,
    int rows, size_t plane)
{
    int idx = blockIdx.x * blockDim.x + threadIdx.x;
    int r = idx / (KP / 8);
    int u = idx % (KP / 8);
    if (r >= rows) return;
    int k = u * 8;
    __nv_bfloat16 h0[8], h1[8], h2[8];
#pragma unroll
    for (int i = 0; i < 8; i++) {
        float x = (k + i < K_DIM) ? src[(size_t)r * K_DIM + k + i] : 0.0f;
        __nv_bfloat16 a = __float2bfloat16(x);
        float r1 = x - __bfloat162float(a);
        __nv_bfloat16 b = __float2bfloat16(r1);
        float r2 = r1 - __bfloat162float(b);
        h0[i] = a; h1[i] = b; h2[i] = __float2bfloat16(r2);
    }
    size_t off = (size_t)r * KP + k;
    *(uint4*)(dst + off)             = *(uint4*)h0;
    *(uint4*)(dst + plane + off)     = *(uint4*)h1;
    *(uint4*)(dst + 2 * plane + off) = *(uint4*)h2;
}

// ---------------------------------------------------------------------------
// Hybrid GEMM. CTA = 128x128 tile of C[m,n] = sum_k A[m,k]*W[n,k].
//  warps 0-3 (1/SMSP): cols [0,96)  bit-exact fp32 FFMA
//  warps 4-7 (1/SMSP): cols [96,128) bf16 3-split, 6 products, mma.sync
// ---------------------------------------------------------------------------
// tensor smem: 3 stages x (3 A planes 128x80B + 3 B planes 32x80B)
#define T_APL     10240
#define T_BPL     2560
#define T_STAGE   (3 * T_APL + 3 * T_BPL)     // 38400
#define T_NST     3
#define T_NCH     (KP / 32)                   // 22
// fp32 smem (floats), after tensor region
#define FP_OFF    (T_NST * T_STAGE)           // 115200 bytes
#define AS_STRIDE 132
#define BS_STRIDE 100
#define AS_OFF_F  (FP_OFF / 4)
#define BS_OFF_F  (FP_OFF / 4 + 16 * AS_STRIDE)
#define DYN_SMEM  (FP_OFF + (16 * AS_STRIDE + 16 * BS_STRIDE) * 4)  // 130048
#define F_NCH     44                          // 704/16

__device__ __forceinline__ uint32_t smem_u32(const void* p) {
    uint32_t a;
    asm("{ .reg .u64 t; cvta.to.shared.u64 t, %1; cvt.u32.u64 %0, t; }" : "=r"(a) : "l"(p));
    return a;
}
__device__ __forceinline__ void ldsm_x4(uint32_t addr, uint32_t& r0, uint32_t& r1,
                                        uint32_t& r2, uint32_t& r3) {
    asm volatile("ldmatrix.sync.aligned.m8n8.x4.shared.b16 {%0,%1,%2,%3}, [%4];"
                 : "=r"(r0), "=r"(r1), "=r"(r2), "=r"(r3) : "r"(addr));
}
__device__ __forceinline__ void mma16816(float* d, const uint32_t* a, const uint32_t* b) {
    asm volatile(
        "mma.sync.aligned.m16n8k16.row.col.f32.bf16.bf16.f32 "
        "{%0,%1,%2,%3}, {%4,%5,%6,%7}, {%8,%9}, {%0,%1,%2,%3};"
        : "+f"(d[0]), "+f"(d[1]), "+f"(d[2]), "+f"(d[3])
        : "r"(a[0]), "r"(a[1]), "r"(a[2]), "r"(a[3]), "r"(b[0]), "r"(b[1]));
}
__device__ __forceinline__ void bar_named(int id, int cnt) {
    asm volatile("bar.sync %0, %1;" :: "r"(id), "r"(cnt) : "memory");
}

// tensor stage load: chunk of 32 k (128 threads, 15 x 16B each)
__device__ __forceinline__ void t_load_stage(
    int chunk, int s, int ltid, int m0, int n0, uint32_t smem_base,
    const __nv_bfloat16* __restrict__ Asp, const __nv_bfloat16* __restrict__ Bsp)
{
    const int k0 = chunk * 32;
    const uint32_t sb = smem_base + s * T_STAGE;
#pragma unroll
    for (int it = 0; it < 15; ++it) {
        int idx = ltid + it * 128;            // 0..1919
        const __nv_bfloat16* src;
        uint32_t dst;
        if (idx < 1536) {
            int tile = idx >> 9, rem = idx & 511, r = rem >> 2, u = rem & 3;
            src = Asp + (size_t)tile * A_PLANE + (size_t)(m0 + r) * KP + k0 + u * 8;
            dst = sb + tile * T_APL + r * 80 + u * 16;
        } else {
            int ib = idx - 1536;
            int tile = ib >> 7, rem = ib & 127, r = rem >> 2, u = rem & 3;
            src = Bsp + (size_t)tile * B_PLANE + (size_t)(n0 + 96 + r) * KP + k0 + u * 8;
            dst = sb + 3 * T_APL + tile * T_BPL + r * 80 + u * 16;
        }
        asm volatile("cp.async.cg.shared.global [%0], [%1], 16;" :: "r"(dst), "l"(src));
    }
    asm volatile("cp.async.commit_group;" ::: "memory");
}

__global__ __launch_bounds__(256, 1) void gemm_hybrid_kernel(
    const float* __restrict__ X,              // [M, 700]
    const float* __restrict__ W,              // [N, 700]
    const __nv_bfloat16* __restrict__ Asp,
    const __nv_bfloat16* __restrict__ Bsp,
    float* __restrict__ C)
{
    extern __shared__ __align__(128) char smem[];
    const uint32_t smem_base = smem_u32(smem);
    float* smf = (float*)smem;                // float view for fp32 tiles
    const int tid  = threadIdx.x;
    const int lane = tid & 31;
    const int wid  = tid >> 5;
    const int m0   = blockIdx.y * 128;
    const int n0   = blockIdx.x * 128;

    if (wid < 4) {
        // =================== fp32 group: cols [0,96) =======================
        const int ltid = tid;                 // 0..127
        const int msub = lane >> 3;           // 0..3
        const int nsub = lane & 7;            // 0..7
        const int mloc = wid * 32 + msub * 8; // row base in tile
        const int nloc = nsub * 12;           // col base (0..84)

        float acc[8][12];
#pragma unroll
        for (int i = 0; i < 8; i++)
#pragma unroll
            for (int j = 0; j < 12; j++) acc[i][j] = 0.f;

        float4 av[4], bv[3];
        // prefetch chunk 0
        {
            const int k0 = 0;
#pragma unroll
            for (int l = 0; l < 4; ++l) {
                int f = ltid + l * 128, row = f >> 2, u = f & 3, kg = k0 + u * 4;
                av[l] = (kg < K_DIM) ? *(const float4*)(X + (size_t)(m0 + row) * K_DIM + kg)
                                     : make_float4(0, 0, 0, 0);
            }
#pragma unroll
            for (int l = 0; l < 3; ++l) {
                int f = ltid + l * 128, row = f >> 2, u = f & 3, kg = k0 + u * 4;
                bv[l] = (kg < K_DIM) ? *(const float4*)(W + (size_t)(n0 + row) * K_DIM + kg)
                                     : make_float4(0, 0, 0, 0);
            }
        }

        for (int c = 0; c < F_NCH; ++c) {
            // store prefetched regs -> smem (transposed to [k][m]/[k][n])
#pragma unroll
            for (int l = 0; l < 4; ++l) {
                int f = ltid + l * 128, row = f >> 2, u = f & 3;
                smf[AS_OFF_F + (u * 4 + 0) * AS_STRIDE + row] = av[l].x;
                smf[AS_OFF_F + (u * 4 + 1) * AS_STRIDE + row] = av[l].y;
                smf[AS_OFF_F + (u * 4 + 2) * AS_STRIDE + row] = av[l].z;
                smf[AS_OFF_F + (u * 4 + 3) * AS_STRIDE + row] = av[l].w;
            }
#pragma unroll
            for (int l = 0; l < 3; ++l) {
                int f = ltid + l * 128, row = f >> 2, u = f & 3;
                smf[BS_OFF_F + (u * 4 + 0) * BS_STRIDE + row] = bv[l].x;
                smf[BS_OFF_F + (u * 4 + 1) * BS_STRIDE + row] = bv[l].y;
                smf[BS_OFF_F + (u * 4 + 2) * BS_STRIDE + row] = bv[l].z;
                smf[BS_OFF_F + (u * 4 + 3) * BS_STRIDE + row] = bv[l].w;
            }
            bar_named(1, 128);

            // prefetch next chunk
            if (c + 1 < F_NCH) {
                const int k0 = (c + 1) * 16;
#pragma unroll
                for (int l = 0; l < 4; ++l) {
                    int f = ltid + l * 128, row = f >> 2, u = f & 3, kg = k0 + u * 4;
                    av[l] = (kg < K_DIM) ? *(const float4*)(X + (size_t)(m0 + row) * K_DIM + kg)
                                         : make_float4(0, 0, 0, 0);
                }
#pragma unroll
                for (int l = 0; l < 3; ++l) {
                    int f = ltid + l * 128, row = f >> 2, u = f & 3, kg = k0 + u * 4;
                    bv[l] = (kg < K_DIM) ? *(const float4*)(W + (size_t)(n0 + row) * K_DIM + kg)
                                         : make_float4(0, 0, 0, 0);
                }
            }

            // compute 16 k-steps (ascending k -> bit-exact chain per (m,n))
#pragma unroll
            for (int k = 0; k < 16; ++k) {
                float4 a0 = *(float4*)&smf[AS_OFF_F + k * AS_STRIDE + mloc];
                float4 a1 = *(float4*)&smf[AS_OFF_F + k * AS_STRIDE + mloc + 4];
                float4 b0 = *(float4*)&smf[BS_OFF_F + k * BS_STRIDE + nloc];
                float4 b1 = *(float4*)&smf[BS_OFF_F + k * BS_STRIDE + nloc + 4];
                float4 b2 = *(float4*)&smf[BS_OFF_F + k * BS_STRIDE + nloc + 8];
                float a[8] = {a0.x, a0.y, a0.z, a0.w, a1.x, a1.y, a1.z, a1.w};
                float b[12] = {b0.x, b0.y, b0.z, b0.w, b1.x, b1.y, b1.z, b1.w,
                               b2.x, b2.y, b2.z, b2.w};
#pragma unroll
                for (int i = 0; i < 8; ++i)
#pragma unroll
                    for (int j = 0; j < 12; ++j)
                        acc[i][j] = fmaf(a[i], b[j], acc[i][j]);
            }
            bar_named(1, 128);
        }

        // epilogue: cols n0 + nloc + 0..11
#pragma unroll
        for (int i = 0; i < 8; ++i) {
            float* cp = C + (size_t)(m0 + mloc + i) * N_DIM + n0 + nloc;
            *(float4*)(cp + 0) = *(float4*)&acc[i][0];
            *(float4*)(cp + 4) = *(float4*)&acc[i][4];
            *(float4*)(cp + 8) = *(float4*)&acc[i][8];
        }
    } else {
        // =================== tensor group: cols [96,128) ===================
        const int ltid = tid - 128;           // 0..127
        const int wtw  = wid - 4;             // 0..3, rows wtw*32..+32

        float acc[2][4][4];
#pragma unroll
        for (int i = 0; i < 2; i++)
#pragma unroll
            for (int j = 0; j < 4; j++)
#pragma unroll
                for (int f = 0; f < 4; f++) acc[i][j][f] = 0.f;

        t_load_stage(0, 0, ltid, m0, n0, smem_base, Asp, Bsp);
        t_load_stage(1, 1, ltid, m0, n0, smem_base, Asp, Bsp);

        const uint32_t a_row = lane & 15;
        const uint32_t a_kb  = ((lane >> 4) & 1) * 16;
        const uint32_t b_row = ((lane >> 4) & 1) * 8 + (lane & 7);
        const uint32_t b_kb  = ((lane >> 3) & 1) * 16;

        for (int c = 0; c < T_NCH; ++c) {
            const int s = c % T_NST;
            if (c == T_NCH - 1)
                asm volatile("cp.async.wait_group 0;" ::: "memory");
            else
                asm volatile("cp.async.wait_group 1;" ::: "memory");
            bar_named(2, 128);

            if (c + 2 < T_NCH)
                t_load_stage(c + 2, (c + 2) % T_NST, ltid, m0, n0, smem_base, Asp, Bsp);

            const uint32_t sA = smem_base + s * T_STAGE;
            const uint32_t sB = sA + 3 * T_APL;
#pragma unroll
            for (int ks = 0; ks < 2; ++ks) {
                uint32_t bf[3][4][2];
#pragma unroll
                for (int q = 0; q < 3; ++q)
#pragma unroll
                    for (int jb = 0; jb < 2; ++jb) {
                        uint32_t addr = sB + q * T_BPL + (b_row + jb * 16) * 80
                                      + ks * 32 + b_kb;
                        ldsm_x4(addr, bf[q][2 * jb][0], bf[q][2 * jb][1],
                                      bf[q][2 * jb + 1][0], bf[q][2 * jb + 1][1]);
                    }
#pragma unroll
                for (int p = 0; p < 3; ++p) {
                    uint32_t af[2][4];
#pragma unroll
                    for (int im = 0; im < 2; ++im) {
                        uint32_t addr = sA + p * T_APL
                                      + (wtw * 32 + im * 16 + a_row) * 80 + ks * 32 + a_kb;
                        ldsm_x4(addr, af[im][0], af[im][1], af[im][2], af[im][3]);
                    }
#pragma unroll
                    for (int q = 0; q < 3; ++q) {
                        if (p + q > 2) continue;
#pragma unroll
                        for (int im = 0; im < 2; ++im)
#pragma unroll
                            for (int jn = 0; jn < 4; ++jn)
                                mma16816(acc[im][jn], af[im], bf[q][jn]);
                    }
                }
            }
            bar_named(2, 128);
        }

        // epilogue: cols n0 + 96 + jn*8 + ...
        const int erow = lane >> 2;
        const int ecol = (lane & 3) * 2;
#pragma unroll
        for (int im = 0; im < 2; ++im)
#pragma unroll
            for (int jn = 0; jn < 4; ++jn) {
                float* cp = C + (size_t)(m0 + wtw * 32 + im * 16 + erow) * N_DIM
                              + n0 + 96 + jn * 8 + ecol;
                *(float2*)cp = make_float2(acc[im][jn][0], acc[im][jn][1]);
                *(float2*)(cp + 8 * N_DIM) = make_float2(acc[im][jn][2], acc[im][jn][3]);
            }
    }
}

// ---------------------------------------------------------------------------
// LIF scan + flag (only tensor-computed cols (h&127)>=96 can be inexact)
// ---------------------------------------------------------------------------
__global__ __launch_bounds__(256) void lif_scan_flag_kernel(
    const float* __restrict__ inp, float* __restrict__ Uo,
    float* __restrict__ So, unsigned char* __restrict__ flags)
{
    int idx = blockIdx.x * blockDim.x + threadIdx.x;
    int b = idx >> 10;
    int h = idx & (N_DIM - 1);
    size_t base = (size_t)b * T_STEPS * N_DIM + h;
    const float* ip = inp + base;
    float* up = Uo + base;
    float* sp = So + base;
    const bool tc_col = (h & 127) >= 96;

    up[0] = 0.0f;
    sp[0] = 0.0f;
    float H = 0.f, I = 0.f, U = 0.f, S = 0.f;
    int flagged = 0;
#pragma unroll 4
    for (int t = 1; t < T_STEPS; t++) {
        float x  = ip[(size_t)(t - 1) * N_DIM];
        float Hn = PHI_C * H + x;
        float In = GAMMA_C * I + H;
        float Un = BETA_C * (U - I) - S;
        float Sn = (Un > U_TH_C) ? 1.0f : 0.0f;
        flagged |= (fabsf(Un - U_TH_C) < EPS_FLAG) ? 1 : 0;
        up[(size_t)t * N_DIM] = Un;
        sp[(size_t)t * N_DIM] = Sn;
        H = Hn; I = In; U = Un; S = Sn;
    }
    flags[idx] = (unsigned char)(flagged && tc_col);
}

// ---------------------------------------------------------------------------
// Repair: bit-exact recompute of flagged channels (one block per batch)
// ---------------------------------------------------------------------------
#define NH_BATCH 8
#define RPR_SX    0
#define RPR_SW    16500
#define RPR_SINP  (16500 + 5632)
#define RPR_SMEM  ((16500 + 5632 + 4000) * 4)

__global__ __launch_bounds__(512) void lif_repair_kernel(
    const float* __restrict__ X, const float* __restrict__ W,
    const unsigned char* __restrict__ flags,
    float* __restrict__ Uo, float* __restrict__ So)
{
    extern __shared__ float rsm[];
    float* sX   = rsm + RPR_SX;
    float* sW   = rsm + RPR_SW;
    float* sInp = rsm + RPR_SINP;
    __shared__ int hlist[N_DIM];
    __shared__ int hcount;

    const int b = blockIdx.x;
    const int tid = threadIdx.x;

    if (tid == 0) {
        int cnt = 0;
        for (int h = 0; h < N_DIM; ++h)
            if (flags[b * N_DIM + h]) hlist[cnt++] = h;
        hcount = cnt;
    }
    __syncthreads();
    const int nflag = hcount;

    for (int bi = 0; bi < nflag; bi += NH_BATCH) {
        const int nh = min(NH_BATCH, nflag - bi);
        for (int i = tid; i < nh * 704; i += 512) {
            int j = i / 704, k = i - j * 704;
            sW[j * 704 + k] = (k < K_DIM) ? W[(size_t)hlist[bi + j] * K_DIM + k] : 0.f;
        }
        __syncthreads();

        float c8[NH_BATCH];
#pragma unroll
        for (int j = 0; j < NH_BATCH; ++j) c8[j] = 0.f;

        for (int kc = 0; kc < K_DIM; kc += 32) {
            const int kw = (K_DIM - kc < 32) ? (K_DIM - kc) : 32;
            for (int i = tid; i < T_STEPS * kw; i += 512) {
                int tt = i / kw, kk = i - tt * kw;
                sX[tt * 33 + kk] = X[((size_t)b * T_STEPS + tt) * K_DIM + kc + kk];
            }
            __syncthreads();
            if (tid < T_STEPS) {
#pragma unroll
                for (int j = 0; j < NH_BATCH; ++j) {
                    float c = c8[j];
                    for (int kk = 0; kk < kw; ++kk)
                        c = fmaf(sX[tid * 33 + kk], sW[j * 704 + kc + kk], c);
                    c8[j] = c;
                }
            }
            __syncthreads();
        }
        if (tid < T_STEPS)
#pragma unroll
            for (int j = 0; j < NH_BATCH; ++j)
                if (j < nh) sInp[j * T_STEPS + tid] = c8[j];
        __syncthreads();

        if (tid < nh) {
            const int h = hlist[bi + tid];
            size_t base = (size_t)b * T_STEPS * N_DIM + h;
            Uo[base] = 0.0f;
            So[base] = 0.0f;
            float H = 0.f, I = 0.f, U = 0.f, S = 0.f;
            for (int t = 1; t < T_STEPS; t++) {
                float x  = sInp[tid * T_STEPS + (t - 1)];
                float Hn = PHI_C * H + x;
                float In = GAMMA_C * I + H;
                float Un = BETA_C * (U - I) - S;
                float Sn = (Un > U_TH_C) ? 1.0f : 0.0f;
                Uo[base + (size_t)t * N_DIM] = Un;
                So[base + (size_t)t * N_DIM] = Sn;
                H = Hn; I = In; U = Un; S = Sn;
            }
        }
        __syncthreads();
    }
}

// ---------------------------------------------------------------------------
extern "C" void kernel_launch(void* const* d_in, const int* in_sizes, int n_in,
                              void* d_out, int out_size)
{
    const float* X = (const float*)d_in[0];
    const float* W = (const float*)d_in[1];
    float* out = (float*)d_out;

    float* inputs;           cudaGetSymbolAddress((void**)&inputs, g_inputs);
    __nv_bfloat16* asplit;   cudaGetSymbolAddress((void**)&asplit, g_asplit);
    __nv_bfloat16* bsplit;   cudaGetSymbolAddress((void**)&bsplit, g_bsplit);
    unsigned char* flags;    cudaGetSymbolAddress((void**)&flags, g_flags);

    cudaFuncSetAttribute(gemm_hybrid_kernel,
                         cudaFuncAttributeMaxDynamicSharedMemorySize, DYN_SMEM);
    cudaFuncSetAttribute(lif_repair_kernel,
                         cudaFuncAttributeMaxDynamicSharedMemorySize, RPR_SMEM);

    split_kernel<<<(M_DIM * (KP / 8) + 255) / 256, 256>>>(X, asplit, M_DIM, A_PLANE);
    split_kernel<<<(N_DIM * (KP / 8) + 255) / 256, 256>>>(W, bsplit, N_DIM, B_PLANE);

    dim3 ggrid(N_DIM / 128, M_DIM / 128);     // (8, 500)
    gemm_hybrid_kernel<<<ggrid, 256, DYN_SMEM>>>(X, W, asplit, bsplit, inputs);

    float* Uo = out;
    float* So = out + (size_t)B_BATCH * T_STEPS * N_DIM;
    lif_scan_flag_kernel<<<(B_BATCH * N_DIM) / 256, 256>>>(inputs, Uo, So, flags);
    lif_repair_kernel<<<B_BATCH, 512, RPR_SMEM>>>(X, W, flags, Uo, So);
}